// round 2
// baseline (speedup 1.0000x reference)
#include <cuda_runtime.h>
#include <cuda_bf16.h>
#include <math.h>

// Problem constants
#define B_   16
#define T_   8192
#define V_   256
#define CE_  256
#define CR_  128
#define CS_  256
#define GC_  64
#define L_   12

// Tiling
#define TT   104   // output positions per CTA
#define WP   128   // buffer width (TT + 24 halo)
#define XS   132   // row stride of x/g/h buffers (floats)
#define SKS  105   // skip accumulator row stride
#define NT   512   // threads per CTA
#define O1S  56    // o1 scratch row stride

// smem layout (in floats)
#define OFF_BUFA 0
#define N_BUFA   (128*XS)             // 16896
#define OFF_GBUF (OFF_BUFA + N_BUFA)  // g buffer / h-chunk staging
#define N_GBUF   (64*XS)              // 8448
#define OFF_SKIP (OFF_GBUF + N_GBUF)
#define N_SKIP   (CS_*SKS)            // 26880
#define OFF_WST  (OFF_SKIP + N_SKIP)
#define N_WST    4160
#define OFF_TOK  (OFF_WST + N_WST)
#define SMEM_BYTES ((OFF_TOK)*4 + 132*4)

__device__ __forceinline__ float sigmoidf_(float x) { return 1.0f / (1.0f + expf(-x)); }

__global__ void __launch_bounds__(NT, 1) wavenet_fused(
    const int*   __restrict__ tokens,
    const float* __restrict__ emb,
    const float* __restrict__ w_init, const float* __restrict__ b_init,
    const float* __restrict__ w_dil,  const float* __restrict__ b_dil,
    const float* __restrict__ w_res,  const float* __restrict__ b_res,
    const float* __restrict__ w_skip, const float* __restrict__ b_skip,
    const float* __restrict__ w_out1, const float* __restrict__ b_out1,
    const float* __restrict__ w_out2, const float* __restrict__ b_out2,
    float* __restrict__ out)
{
    extern __shared__ float sm[];
    float* bufA  = sm + OFF_BUFA;   // x activations [128][XS]
    float* gbuf  = sm + OFF_GBUF;   // gate output   [64][XS]  (also h-chunk staging)
    float* skipS = sm + OFF_SKIP;   // skip accum    [256][SKS]
    float* wst   = sm + OFF_WST;    // weight staging
    int*   tokb  = (int*)(sm + OFF_TOK);

    const int tid  = threadIdx.x;
    const int tile = blockIdx.x;
    const int bb   = blockIdx.y;
    const int t0   = tile * TT;
    // buffer position p corresponds to global time t = t0 - 24 + p
    const int pzero = (tile == 0) ? 24 : 0;  // positions with global t<0 must stay 0

    // stage tokens for q in [0,129): global t = t0 - 25 + q
    for (int q = tid; q < WP + 1; q += NT) {
        int t = t0 - 25 + q;
        tokb[q] = (t >= 0 && t < T_) ? tokens[bb * T_ + t] : -1;
    }
    for (int i = tid; i < N_SKIP; i += NT) skipS[i] = 0.0f;

    // conv GEMM thread mapping: 32 channel-groups x 16 position-groups
    const int cg = tid >> 4;      // 0..31
    const int pg = tid & 15;      // 0..15
    const int c0 = 2 * cg;        // output channels {c0, c0+1, c0+64, c0+65}
    const int p0 = 8 * pg;        // positions [p0, p0+8)

    float acc[4][8];

    // ======================= init conv (emb -> x0) =======================
    #pragma unroll
    for (int ic = 0; ic < 4; ++ic)
        #pragma unroll
        for (int j = 0; j < 8; ++j) acc[ic][j] = 0.0f;

    __syncthreads();
    for (int ch = 0; ch < 16; ++ch) {           // ce chunks of 16
        const int ceb = ch * 16;
        // stage h chunk: gbuf[ce][q] = emb[tok[q]][ceb+ce]
        for (int idx = tid; idx < (WP + 1) * 4; idx += NT) {
            int q = idx >> 2; int ce4 = (idx & 3) << 2;
            int tok = tokb[q];
            float4 v = make_float4(0.f, 0.f, 0.f, 0.f);
            if (tok >= 0) v = *reinterpret_cast<const float4*>(emb + tok * CE_ + ceb + ce4);
            gbuf[(ce4 + 0) * XS + q] = v.x;
            gbuf[(ce4 + 1) * XS + q] = v.y;
            gbuf[(ce4 + 2) * XS + q] = v.z;
            gbuf[(ce4 + 3) * XS + q] = v.w;
        }
        // stage w chunk: wst[ce*260 + 2*co + k] = w_init[co][ceb+ce][k]
        for (int idx = tid; idx < 2048; idx += NT) {
            int ce = idx & 15; int co = idx >> 4;
            float2 w2 = *reinterpret_cast<const float2*>(w_init + ((co * CE_ + ceb + ce) << 1));
            wst[ce * 260 + 2 * co]     = w2.x;
            wst[ce * 260 + 2 * co + 1] = w2.y;
        }
        __syncthreads();
        #pragma unroll
        for (int ce = 0; ce < 16; ++ce) {
            const float* hr = gbuf + ce * XS + p0;   // h at q = p0 + j
            float hv[9];
            float4 t4 = *reinterpret_cast<const float4*>(hr);
            hv[0]=t4.x; hv[1]=t4.y; hv[2]=t4.z; hv[3]=t4.w;
            t4 = *reinterpret_cast<const float4*>(hr + 4);
            hv[4]=t4.x; hv[5]=t4.y; hv[6]=t4.z; hv[7]=t4.w;
            hv[8] = hr[8];
            const float* wr = wst + ce * 260 + 2 * c0;
            float4 wlo = *reinterpret_cast<const float4*>(wr);        // c0, c0+1
            float4 whi = *reinterpret_cast<const float4*>(wr + 128);  // c0+64, c0+65
            // out p=p0+j: tap0 -> h[t-1] = hv[j], tap1 -> h[t] = hv[j+1]
            #pragma unroll
            for (int j = 0; j < 8; ++j) {
                acc[0][j] += wlo.x * hv[j] + wlo.y * hv[j + 1];
                acc[1][j] += wlo.z * hv[j] + wlo.w * hv[j + 1];
                acc[2][j] += whi.x * hv[j] + whi.y * hv[j + 1];
                acc[3][j] += whi.z * hv[j] + whi.w * hv[j + 1];
            }
        }
        __syncthreads();
    }
    // bias + masked store
    #pragma unroll
    for (int ic = 0; ic < 4; ++ic) {
        int co = (ic < 2) ? (c0 + ic) : (c0 + 62 + ic);
        float bi = __ldg(b_init + co);
        #pragma unroll
        for (int j = 0; j < 8; ++j) {
            int p = p0 + j;
            bufA[co * XS + p] = (p < pzero) ? 0.0f : (acc[ic][j] + bi);
        }
    }
    __syncthreads();

    // skip-GEMM thread mapping
    const int sg  = tid >> 3;        // 0..63
    const int jg  = tid & 7;         // 0..7
    const int cs0 = 4 * sg;
    const int j0  = 13 * jg;

    // ============================ layers ============================
    for (int l = 0; l < L_; ++l) {
        // ---- dilated conv (k=2, d=2): xc = W0 x[t-2] + W1 x[t] ----
        #pragma unroll
        for (int ic = 0; ic < 4; ++ic)
            #pragma unroll
            for (int j = 0; j < 8; ++j) acc[ic][j] = 0.0f;

        const float* wd = w_dil + (size_t)l * CR_ * CR_ * 2;
        for (int ch = 0; ch < 8; ++ch) {        // ci chunks of 16
            const int cib = ch * 16;
            for (int idx = tid; idx < 2048; idx += NT) {
                int ci = idx & 15; int co = idx >> 4;
                float2 w2 = *reinterpret_cast<const float2*>(wd + ((co * CR_ + cib + ci) << 1));
                wst[ci * 260 + 2 * co]     = w2.x;
                wst[ci * 260 + 2 * co + 1] = w2.y;
            }
            __syncthreads();
            #pragma unroll
            for (int ci = 0; ci < 16; ++ci) {
                const float* xr = bufA + (cib + ci) * XS + p0;
                float xv[10];                         // xv[j] = x[p0-2+j]
                if (p0 >= 2) { xv[0] = xr[-2]; xv[1] = xr[-1]; }
                else         { xv[0] = 0.0f;  xv[1] = 0.0f;  }
                float4 t4 = *reinterpret_cast<const float4*>(xr);
                xv[2]=t4.x; xv[3]=t4.y; xv[4]=t4.z; xv[5]=t4.w;
                t4 = *reinterpret_cast<const float4*>(xr + 4);
                xv[6]=t4.x; xv[7]=t4.y; xv[8]=t4.z; xv[9]=t4.w;
                const float* wr = wst + ci * 260 + 2 * c0;
                float4 wlo = *reinterpret_cast<const float4*>(wr);
                float4 whi = *reinterpret_cast<const float4*>(wr + 128);
                #pragma unroll
                for (int j = 0; j < 8; ++j) {
                    acc[0][j] += wlo.x * xv[j] + wlo.y * xv[j + 2];
                    acc[1][j] += wlo.z * xv[j] + wlo.w * xv[j + 2];
                    acc[2][j] += whi.x * xv[j] + whi.y * xv[j + 2];
                    acc[3][j] += whi.z * xv[j] + whi.w * xv[j + 2];
                }
            }
            __syncthreads();
        }
        // ---- gate: g[c] = tanh(xc[c]) * sigmoid(xc[c+64]), c in [0,64) ----
        {
            const float* bd = b_dil + l * CR_;
            float b0 = __ldg(bd + c0), b1 = __ldg(bd + c0 + 1);
            float b2 = __ldg(bd + c0 + 64), b3 = __ldg(bd + c0 + 65);
            #pragma unroll
            for (int j = 0; j < 8; ++j) {
                float g0 = tanhf(acc[0][j] + b0) * sigmoidf_(acc[2][j] + b2);
                float g1 = tanhf(acc[1][j] + b1) * sigmoidf_(acc[3][j] + b3);
                gbuf[c0 * XS + p0 + j]       = g0;
                gbuf[(c0 + 1) * XS + p0 + j] = g1;
            }
        }
        __syncthreads();

        // ---- skip accumulation: skip[cs,j] += sum_gc w_skip[cs,gc] g[gc, 24+j] ----
        {
            const float* wsk = w_skip + (size_t)l * CS_ * GC_;
            float sacc[4][13];
            #pragma unroll
            for (int ii = 0; ii < 4; ++ii)
                #pragma unroll
                for (int jj = 0; jj < 13; ++jj) sacc[ii][jj] = 0.0f;
            for (int gch = 0; gch < 4; ++gch) {   // gc chunks of 16
                const int gcb = gch * 16;
                for (int idx = tid; idx < 4096; idx += NT) {
                    int gc = idx & 15; int cs = idx >> 4;
                    wst[gc * 260 + cs] = wsk[cs * GC_ + gcb + gc];
                }
                __syncthreads();
                #pragma unroll
                for (int gc = 0; gc < 16; ++gc) {
                    float4 wv = *reinterpret_cast<const float4*>(wst + gc * 260 + cs0);
                    const float* gr = gbuf + (gcb + gc) * XS + 24 + j0;
                    #pragma unroll
                    for (int jj = 0; jj < 13; ++jj) {
                        float gv = gr[jj];
                        sacc[0][jj] += wv.x * gv;
                        sacc[1][jj] += wv.y * gv;
                        sacc[2][jj] += wv.z * gv;
                        sacc[3][jj] += wv.w * gv;
                    }
                }
                __syncthreads();
            }
            const float* bsk = b_skip + l * CS_;
            #pragma unroll
            for (int ii = 0; ii < 4; ++ii) {
                float bbv = __ldg(bsk + cs0 + ii);
                float* sp = skipS + (cs0 + ii) * SKS + j0;
                #pragma unroll
                for (int jj = 0; jj < 13; ++jj) sp[jj] += sacc[ii][jj] + bbv;
            }
        }

        // ---- residual: x = x + W_res g (+b) ----
        {
            const float* wrp = w_res + (size_t)l * CR_ * GC_;
            float racc[4][8];
            #pragma unroll
            for (int ic = 0; ic < 4; ++ic)
                #pragma unroll
                for (int j = 0; j < 8; ++j) racc[ic][j] = 0.0f;
            for (int gch = 0; gch < 2; ++gch) {   // gc chunks of 32
                const int gcb = gch * 32;
                __syncthreads();  // ensure skip readers done with wst
                for (int idx = tid; idx < 4096; idx += NT) {
                    int gc = idx & 31; int co = idx >> 5;
                    wst[gc * 130 + co] = wrp[co * GC_ + gcb + gc];
                }
                __syncthreads();
                #pragma unroll
                for (int gc = 0; gc < 32; ++gc) {
                    const float* gr = gbuf + (gcb + gc) * XS + p0;
                    float4 ga = *reinterpret_cast<const float4*>(gr);
                    float4 gb = *reinterpret_cast<const float4*>(gr + 4);
                    float gv[8] = {ga.x, ga.y, ga.z, ga.w, gb.x, gb.y, gb.z, gb.w};
                    const float* wrow = wst + gc * 130;
                    float2 wlo = *reinterpret_cast<const float2*>(wrow + c0);
                    float2 whi = *reinterpret_cast<const float2*>(wrow + c0 + 64);
                    #pragma unroll
                    for (int j = 0; j < 8; ++j) {
                        racc[0][j] += wlo.x * gv[j];
                        racc[1][j] += wlo.y * gv[j];
                        racc[2][j] += whi.x * gv[j];
                        racc[3][j] += whi.y * gv[j];
                    }
                }
            }
            __syncthreads();
            const float* br = b_res + l * CR_;
            #pragma unroll
            for (int ic = 0; ic < 4; ++ic) {
                int co = (ic < 2) ? (c0 + ic) : (c0 + 62 + ic);
                float bi = __ldg(br + co);
                #pragma unroll
                for (int j = 0; j < 8; ++j) {
                    int p = p0 + j;
                    float v = (p < pzero) ? 0.0f : (bufA[co * XS + p] + racc[ic][j] + bi);
                    bufA[co * XS + p] = v;
                }
            }
        }
        __syncthreads();
    }

    // ======================= output head =======================
    // s = relu(skip/12) in place
    for (int i = tid; i < N_SKIP; i += NT) {
        float v = skipS[i] * (1.0f / 12.0f);
        skipS[i] = v > 0.0f ? v : 0.0f;
    }

    float* o1buf = bufA;                 // reuse, [256][O1S]
    const int c0b = 2 * (tid >> 2);      // 2 output channels per thread
    const int jg2 = tid & 3;
    const int j0b = 13 * jg2;            // 13 cols per thread (52/half)

    for (int half = 0; half < 2; ++half) {
        const int jbase = half * 52;
        // ---- out1 ----
        float a2[2][13];
        #pragma unroll
        for (int ii = 0; ii < 2; ++ii)
            #pragma unroll
            for (int jj = 0; jj < 13; ++jj) a2[ii][jj] = 0.0f;
        for (int kch = 0; kch < 16; ++kch) {
            const int kb = kch * 16;
            __syncthreads();
            for (int idx = tid; idx < 4096; idx += NT) {
                int k = idx & 15; int c = idx >> 4;
                wst[k * 260 + c] = w_out1[c * CS_ + kb + k];
            }
            __syncthreads();
            #pragma unroll
            for (int k = 0; k < 16; ++k) {
                float2 wv = *reinterpret_cast<const float2*>(wst + k * 260 + c0b);
                const float* sr = skipS + (kb + k) * SKS + jbase + j0b;
                #pragma unroll
                for (int jj = 0; jj < 13; ++jj) {
                    float sv = sr[jj];
                    a2[0][jj] += wv.x * sv;
                    a2[1][jj] += wv.y * sv;
                }
            }
        }
        __syncthreads();
        #pragma unroll
        for (int ii = 0; ii < 2; ++ii) {
            float bi = __ldg(b_out1 + c0b + ii);
            #pragma unroll
            for (int jj = 0; jj < 13; ++jj) {
                float v = a2[ii][jj] + bi;
                o1buf[(c0b + ii) * O1S + j0b + jj] = v > 0.0f ? v : 0.0f;
            }
        }
        __syncthreads();
        // ---- out2 ----
        float a3[2][13];
        #pragma unroll
        for (int ii = 0; ii < 2; ++ii)
            #pragma unroll
            for (int jj = 0; jj < 13; ++jj) a3[ii][jj] = 0.0f;
        for (int kch = 0; kch < 16; ++kch) {
            const int kb = kch * 16;
            __syncthreads();
            for (int idx = tid; idx < 4096; idx += NT) {
                int k = idx & 15; int c = idx >> 4;
                wst[k * 260 + c] = w_out2[c * CS_ + kb + k];
            }
            __syncthreads();
            #pragma unroll
            for (int k = 0; k < 16; ++k) {
                float2 wv = *reinterpret_cast<const float2*>(wst + k * 260 + c0b);
                const float* orr = o1buf + (kb + k) * O1S + j0b;
                #pragma unroll
                for (int jj = 0; jj < 13; ++jj) {
                    float ov = orr[jj];
                    a3[0][jj] += wv.x * ov;
                    a3[1][jj] += wv.y * ov;
                }
            }
        }
        // write to gmem
        #pragma unroll
        for (int ii = 0; ii < 2; ++ii) {
            float bi = __ldg(b_out2 + c0b + ii);
            float* orow = out + ((size_t)bb * V_ + c0b + ii) * T_;
            #pragma unroll
            for (int jj = 0; jj < 13; ++jj) {
                int t = t0 + jbase + j0b + jj;
                if (t < T_) orow[t] = a3[ii][jj] + bi;
            }
        }
        __syncthreads();
    }
}

extern "C" void kernel_launch(void* const* d_in, const int* in_sizes, int n_in,
                              void* d_out, int out_size) {
    const int*   tokens = (const int*)  d_in[0];
    const float* emb    = (const float*)d_in[1];
    const float* w_init = (const float*)d_in[2];
    const float* b_init = (const float*)d_in[3];
    const float* w_dil  = (const float*)d_in[4];
    const float* b_dil  = (const float*)d_in[5];
    const float* w_res  = (const float*)d_in[6];
    const float* b_res  = (const float*)d_in[7];
    const float* w_skip = (const float*)d_in[8];
    const float* b_skip = (const float*)d_in[9];
    const float* w_out1 = (const float*)d_in[10];
    const float* b_out1 = (const float*)d_in[11];
    const float* w_out2 = (const float*)d_in[12];
    const float* b_out2 = (const float*)d_in[13];
    float* out = (float*)d_out;

    cudaFuncSetAttribute(wavenet_fused, cudaFuncAttributeMaxDynamicSharedMemorySize, SMEM_BYTES);
    dim3 grid((T_ + TT - 1) / TT, B_);
    wavenet_fused<<<grid, NT, SMEM_BYTES>>>(
        tokens, emb, w_init, b_init, w_dil, b_dil, w_res, b_res,
        w_skip, b_skip, w_out1, b_out1, w_out2, b_out2, out);
}

// round 3
// speedup vs baseline: 1.0222x; 1.0222x over previous
#include <cuda_runtime.h>
#include <cuda_bf16.h>
#include <math.h>

// Problem constants
#define B_   16
#define T_   8192
#define V_   256
#define CE_  256
#define CR_  128
#define CS_  256
#define GC_  64
#define L_   12

// Tiling
#define TT   104   // output positions per CTA
#define WP   128   // buffer width (TT + 24 halo)
#define XS   132   // row stride of x/g/h buffers (floats)
#define SKS  106   // skip accumulator row stride (even for 8B-aligned pairs)
#define NT   512   // threads per CTA
#define O1S  56    // o1 scratch row stride (even)

// smem layout (in floats)
#define OFF_BUFA 0
#define N_BUFA   (128*XS)             // 16896
#define OFF_GBUF (OFF_BUFA + N_BUFA)
#define N_GBUF   (64*XS)              // 8448
#define OFF_SKIP (OFF_GBUF + N_GBUF)
#define N_SKIP   (CS_*SKS)            // 27136
#define OFF_WST  (OFF_SKIP + N_SKIP)
#define N_WST    4160
#define OFF_TOK  (OFF_WST + N_WST)
#define SMEM_BYTES ((OFF_TOK)*4 + 132*4)   // 227,088 B

typedef unsigned long long u64;

__device__ __forceinline__ u64 pk2(float lo, float hi) {
    u64 r; asm("mov.b64 %0, {%1,%2};" : "=l"(r) : "f"(lo), "f"(hi)); return r;
}
__device__ __forceinline__ u64 bc2(float x) { return pk2(x, x); }
__device__ __forceinline__ void fma2(u64& d, u64 a, u64 b) {
    asm("fma.rn.f32x2 %0, %1, %2, %0;" : "+l"(d) : "l"(a), "l"(b));
}
__device__ __forceinline__ u64 add2(u64 a, u64 b) {
    u64 r; asm("add.rn.f32x2 %0, %1, %2;" : "=l"(r) : "l"(a), "l"(b)); return r;
}
__device__ __forceinline__ float2 up2(u64 a) {
    float2 f; asm("mov.b64 {%0,%1}, %2;" : "=f"(f.x), "=f"(f.y) : "l"(a)); return f;
}
__device__ __forceinline__ float sigmoidf_(float x) { return 1.0f / (1.0f + expf(-x)); }

__global__ void __launch_bounds__(NT, 1) wavenet_fused(
    const int*   __restrict__ tokens,
    const float* __restrict__ emb,
    const float* __restrict__ w_init, const float* __restrict__ b_init,
    const float* __restrict__ w_dil,  const float* __restrict__ b_dil,
    const float* __restrict__ w_res,  const float* __restrict__ b_res,
    const float* __restrict__ w_skip, const float* __restrict__ b_skip,
    const float* __restrict__ w_out1, const float* __restrict__ b_out1,
    const float* __restrict__ w_out2, const float* __restrict__ b_out2,
    float* __restrict__ out)
{
    extern __shared__ float sm[];
    float* bufA  = sm + OFF_BUFA;   // x activations [128][XS]
    float* gbuf  = sm + OFF_GBUF;   // gate output   [64][XS]  (also h-chunk staging)
    float* skipS = sm + OFF_SKIP;   // skip accum    [256][SKS]
    float* wst   = sm + OFF_WST;    // weight staging
    int*   tokb  = (int*)(sm + OFF_TOK);

    const int tid  = threadIdx.x;
    const int tile = blockIdx.x;
    const int bb   = blockIdx.y;
    const int t0   = tile * TT;
    const int pzero = (tile == 0) ? 24 : 0;  // positions with global t<0 stay 0

    for (int q = tid; q < WP + 1; q += NT) {
        int t = t0 - 25 + q;
        tokb[q] = (t >= 0 && t < T_) ? tokens[bb * T_ + t] : -1;
    }
    for (int i = tid; i < N_SKIP; i += NT) skipS[i] = 0.0f;

    // conv GEMM thread mapping: 32 channel-groups x 16 position-groups
    const int cg = tid >> 4;      // 0..31
    const int pg = tid & 15;      // 0..15
    const int c0 = 2 * cg;        // output channels {c0, c0+1, c0+64, c0+65}
    const int p0 = 8 * pg;        // positions [p0, p0+8), even

    // ======================= init conv (emb -> x0) =======================
    {
        u64 accC[2][8];           // accC[0][j] = {c0,c0+1}@p0+j, accC[1][j] = {c0+64,c0+65}
        #pragma unroll
        for (int r = 0; r < 2; ++r)
            #pragma unroll
            for (int j = 0; j < 8; ++j) accC[r][j] = 0ULL;

        __syncthreads();
        for (int ch = 0; ch < 16; ++ch) {       // ce chunks of 16
            const int ceb = ch * 16;
            for (int idx = tid; idx < (WP + 1) * 4; idx += NT) {
                int q = idx >> 2; int ce4 = (idx & 3) << 2;
                int tok = tokb[q];
                float4 v = make_float4(0.f, 0.f, 0.f, 0.f);
                if (tok >= 0) v = *reinterpret_cast<const float4*>(emb + tok * CE_ + ceb + ce4);
                gbuf[(ce4 + 0) * XS + q] = v.x;
                gbuf[(ce4 + 1) * XS + q] = v.y;
                gbuf[(ce4 + 2) * XS + q] = v.z;
                gbuf[(ce4 + 3) * XS + q] = v.w;
            }
            // tap-split staging: wst[ce*260 + tap*128 + co]
            for (int idx = tid; idx < 2048; idx += NT) {
                int ce = idx & 15; int co = idx >> 4;
                float2 w2 = *reinterpret_cast<const float2*>(w_init + ((co * CE_ + ceb + ce) << 1));
                wst[ce * 260 + co]       = w2.x;
                wst[ce * 260 + 128 + co] = w2.y;
            }
            __syncthreads();
            #pragma unroll
            for (int ce = 0; ce < 16; ++ce) {
                const float* hr = gbuf + ce * XS + p0;
                float hv[9];
                float4 t4 = *reinterpret_cast<const float4*>(hr);
                hv[0]=t4.x; hv[1]=t4.y; hv[2]=t4.z; hv[3]=t4.w;
                t4 = *reinterpret_cast<const float4*>(hr + 4);
                hv[4]=t4.x; hv[5]=t4.y; hv[6]=t4.z; hv[7]=t4.w;
                hv[8] = hr[8];
                u64 hb[9];
                #pragma unroll
                for (int q = 0; q < 9; ++q) hb[q] = bc2(hv[q]);
                const float* wr = wst + ce * 260;
                u64 wt0lo = *reinterpret_cast<const u64*>(wr + c0);
                u64 wt1lo = *reinterpret_cast<const u64*>(wr + 128 + c0);
                u64 wt0hi = *reinterpret_cast<const u64*>(wr + 64 + c0);
                u64 wt1hi = *reinterpret_cast<const u64*>(wr + 192 + c0);
                #pragma unroll
                for (int j = 0; j < 8; ++j) {
                    fma2(accC[0][j], wt0lo, hb[j]);
                    fma2(accC[0][j], wt1lo, hb[j + 1]);
                    fma2(accC[1][j], wt0hi, hb[j]);
                    fma2(accC[1][j], wt1hi, hb[j + 1]);
                }
            }
            __syncthreads();
        }
        float bi0 = __ldg(b_init + c0), bi1 = __ldg(b_init + c0 + 1);
        float bi2 = __ldg(b_init + c0 + 64), bi3 = __ldg(b_init + c0 + 65);
        #pragma unroll
        for (int j = 0; j < 8; ++j) {
            int p = p0 + j;
            bool z = (p < pzero);
            float2 lo = up2(accC[0][j]);
            float2 hi = up2(accC[1][j]);
            bufA[c0 * XS + p]        = z ? 0.0f : (lo.x + bi0);
            bufA[(c0 + 1) * XS + p]  = z ? 0.0f : (lo.y + bi1);
            bufA[(c0 + 64) * XS + p] = z ? 0.0f : (hi.x + bi2);
            bufA[(c0 + 65) * XS + p] = z ? 0.0f : (hi.y + bi3);
        }
    }
    __syncthreads();

    // skip-GEMM thread mapping: 128 ch-groups x 4 col-groups, 2 ch x 26 cols each
    const int cs0 = 2 * (tid >> 2);
    const int j0  = 26 * (tid & 3);

    // ============================ layers ============================
    for (int l = 0; l < L_; ++l) {
        // ---- dilated conv (k=2, d=2): position-pair packed ----
        u64 acc2[4][4];
        #pragma unroll
        for (int ic = 0; ic < 4; ++ic)
            #pragma unroll
            for (int k = 0; k < 4; ++k) acc2[ic][k] = 0ULL;

        const float* wd = w_dil + (size_t)l * CR_ * CR_ * 2;
        for (int ch = 0; ch < 8; ++ch) {        // ci chunks of 16
            const int cib = ch * 16;
            for (int idx = tid; idx < 2048; idx += NT) {
                int ci = idx & 15; int co = idx >> 4;
                float2 w2 = *reinterpret_cast<const float2*>(wd + ((co * CR_ + cib + ci) << 1));
                wst[ci * 260 + 2 * co]     = w2.x;
                wst[ci * 260 + 2 * co + 1] = w2.y;
            }
            __syncthreads();
            #pragma unroll
            for (int ci = 0; ci < 16; ++ci) {
                const float* xr = bufA + (cib + ci) * XS + p0;
                u64 xp[5];
                xp[0] = (p0 >= 2) ? *reinterpret_cast<const u64*>(xr - 2) : 0ULL;
                xp[1] = *reinterpret_cast<const u64*>(xr);
                xp[2] = *reinterpret_cast<const u64*>(xr + 2);
                xp[3] = *reinterpret_cast<const u64*>(xr + 4);
                xp[4] = *reinterpret_cast<const u64*>(xr + 6);
                const float* wr = wst + ci * 260 + 2 * c0;
                float4 wlo = *reinterpret_cast<const float4*>(wr);
                float4 whi = *reinterpret_cast<const float4*>(wr + 128);
                u64 b0 = bc2(wlo.x), b1 = bc2(wlo.y), b2 = bc2(wlo.z), b3 = bc2(wlo.w);
                u64 b4 = bc2(whi.x), b5 = bc2(whi.y), b6 = bc2(whi.z), b7 = bc2(whi.w);
                #pragma unroll
                for (int k = 0; k < 4; ++k) {
                    fma2(acc2[0][k], b0, xp[k]); fma2(acc2[0][k], b1, xp[k + 1]);
                    fma2(acc2[1][k], b2, xp[k]); fma2(acc2[1][k], b3, xp[k + 1]);
                    fma2(acc2[2][k], b4, xp[k]); fma2(acc2[2][k], b5, xp[k + 1]);
                    fma2(acc2[3][k], b6, xp[k]); fma2(acc2[3][k], b7, xp[k + 1]);
                }
            }
            __syncthreads();
        }
        // ---- gate ----
        {
            const float* bd = b_dil + l * CR_;
            float gb0 = __ldg(bd + c0), gb1 = __ldg(bd + c0 + 1);
            float gb2 = __ldg(bd + c0 + 64), gb3 = __ldg(bd + c0 + 65);
            #pragma unroll
            for (int k = 0; k < 4; ++k) {
                float2 a0 = up2(acc2[0][k]);
                float2 a1 = up2(acc2[1][k]);
                float2 a2v = up2(acc2[2][k]);
                float2 a3v = up2(acc2[3][k]);
                float g0a = tanhf(a0.x + gb0) * sigmoidf_(a2v.x + gb2);
                float g0b = tanhf(a0.y + gb0) * sigmoidf_(a2v.y + gb2);
                float g1a = tanhf(a1.x + gb1) * sigmoidf_(a3v.x + gb3);
                float g1b = tanhf(a1.y + gb1) * sigmoidf_(a3v.y + gb3);
                *reinterpret_cast<u64*>(gbuf + c0 * XS + p0 + 2 * k)       = pk2(g0a, g0b);
                *reinterpret_cast<u64*>(gbuf + (c0 + 1) * XS + p0 + 2 * k) = pk2(g1a, g1b);
            }
        }
        __syncthreads();

        // ---- skip accumulation ----
        {
            const float* wsk = w_skip + (size_t)l * CS_ * GC_;
            u64 sacc0[13], sacc1[13];
            #pragma unroll
            for (int kk = 0; kk < 13; ++kk) { sacc0[kk] = 0ULL; sacc1[kk] = 0ULL; }
            for (int gch = 0; gch < 4; ++gch) {
                const int gcb = gch * 16;
                for (int idx = tid; idx < 4096; idx += NT) {
                    int gc = idx & 15; int cs = idx >> 4;
                    wst[gc * 260 + cs] = wsk[cs * GC_ + gcb + gc];
                }
                __syncthreads();
                #pragma unroll
                for (int gc = 0; gc < 16; ++gc) {
                    const float* wrow = wst + gc * 260;
                    u64 wb0 = bc2(wrow[cs0]);
                    u64 wb1 = bc2(wrow[cs0 + 1]);
                    const u64* gr = reinterpret_cast<const u64*>(gbuf + (gcb + gc) * XS + 24 + j0);
                    #pragma unroll
                    for (int kk = 0; kk < 13; ++kk) {
                        u64 gv = gr[kk];
                        fma2(sacc0[kk], wb0, gv);
                        fma2(sacc1[kk], wb1, gv);
                    }
                }
                __syncthreads();
            }
            const float* bsk = b_skip + l * CS_;
            u64 bbp0 = bc2(__ldg(bsk + cs0));
            u64 bbp1 = bc2(__ldg(bsk + cs0 + 1));
            u64* sp0 = reinterpret_cast<u64*>(skipS + cs0 * SKS + j0);
            u64* sp1 = reinterpret_cast<u64*>(skipS + (cs0 + 1) * SKS + j0);
            #pragma unroll
            for (int kk = 0; kk < 13; ++kk) {
                sp0[kk] = add2(sp0[kk], add2(sacc0[kk], bbp0));
                sp1[kk] = add2(sp1[kk], add2(sacc1[kk], bbp1));
            }
        }

        // ---- residual: x = x + W_res g (+b) ----
        {
            const float* wrp = w_res + (size_t)l * CR_ * GC_;
            u64 racc[4][4];
            #pragma unroll
            for (int ic = 0; ic < 4; ++ic)
                #pragma unroll
                for (int k = 0; k < 4; ++k) racc[ic][k] = 0ULL;
            for (int gch = 0; gch < 2; ++gch) {
                const int gcb = gch * 32;
                __syncthreads();
                for (int idx = tid; idx < 4096; idx += NT) {
                    int gc = idx & 31; int co = idx >> 5;
                    wst[gc * 130 + co] = wrp[co * GC_ + gcb + gc];
                }
                __syncthreads();
                #pragma unroll
                for (int gc = 0; gc < 32; ++gc) {
                    const u64* gr = reinterpret_cast<const u64*>(gbuf + (gcb + gc) * XS + p0);
                    u64 g0 = gr[0], g1 = gr[1], g2 = gr[2], g3 = gr[3];
                    const float* wrow = wst + gc * 130;
                    float2 wlo = *reinterpret_cast<const float2*>(wrow + c0);
                    float2 whi = *reinterpret_cast<const float2*>(wrow + c0 + 64);
                    u64 w0 = bc2(wlo.x), w1 = bc2(wlo.y), w2 = bc2(whi.x), w3 = bc2(whi.y);
                    fma2(racc[0][0], w0, g0); fma2(racc[0][1], w0, g1);
                    fma2(racc[0][2], w0, g2); fma2(racc[0][3], w0, g3);
                    fma2(racc[1][0], w1, g0); fma2(racc[1][1], w1, g1);
                    fma2(racc[1][2], w1, g2); fma2(racc[1][3], w1, g3);
                    fma2(racc[2][0], w2, g0); fma2(racc[2][1], w2, g1);
                    fma2(racc[2][2], w2, g2); fma2(racc[2][3], w2, g3);
                    fma2(racc[3][0], w3, g0); fma2(racc[3][1], w3, g1);
                    fma2(racc[3][2], w3, g2); fma2(racc[3][3], w3, g3);
                }
            }
            __syncthreads();
            const float* br = b_res + l * CR_;
            if (pzero == 0) {
                #pragma unroll
                for (int ic = 0; ic < 4; ++ic) {
                    int co = (ic < 2) ? (c0 + ic) : (c0 + 62 + ic);
                    u64 bp = bc2(__ldg(br + co));
                    u64* xrow = reinterpret_cast<u64*>(bufA + co * XS + p0);
                    #pragma unroll
                    for (int k = 0; k < 4; ++k)
                        xrow[k] = add2(xrow[k], add2(racc[ic][k], bp));
                }
            } else {
                #pragma unroll
                for (int ic = 0; ic < 4; ++ic) {
                    int co = (ic < 2) ? (c0 + ic) : (c0 + 62 + ic);
                    float bi = __ldg(br + co);
                    #pragma unroll
                    for (int k = 0; k < 4; ++k) {
                        float2 rv = up2(racc[ic][k]);
                        int p = p0 + 2 * k;
                        float v0 = (p < pzero) ? 0.0f : (bufA[co * XS + p] + rv.x + bi);
                        float v1 = (p + 1 < pzero) ? 0.0f : (bufA[co * XS + p + 1] + rv.y + bi);
                        bufA[co * XS + p]     = v0;
                        bufA[co * XS + p + 1] = v1;
                    }
                }
            }
        }
        __syncthreads();
    }

    // ======================= output head =======================
    for (int i = tid; i < N_SKIP; i += NT) {
        float v = skipS[i] * (1.0f / 12.0f);
        skipS[i] = v > 0.0f ? v : 0.0f;
    }

    float* o1buf = bufA;                 // reuse, [256][O1S]
    const int c0h = tid >> 1;            // one output channel per thread
    const int jh  = 26 * (tid & 1);      // 26 cols per thread (52 per half)

    for (int half = 0; half < 2; ++half) {
        const int jbase = half * 52;
        // ---- out1 ----
        u64 a2p[13];
        #pragma unroll
        for (int kk = 0; kk < 13; ++kk) a2p[kk] = 0ULL;
        for (int kch = 0; kch < 16; ++kch) {
            const int kb = kch * 16;
            __syncthreads();
            for (int idx = tid; idx < 4096; idx += NT) {
                int k = idx & 15; int c = idx >> 4;
                wst[k * 260 + c] = w_out1[c * CS_ + kb + k];
            }
            __syncthreads();
            #pragma unroll
            for (int k = 0; k < 16; ++k) {
                u64 wb = bc2(wst[k * 260 + c0h]);
                const u64* sr = reinterpret_cast<const u64*>(skipS + (kb + k) * SKS + jbase + jh);
                #pragma unroll
                for (int kk = 0; kk < 13; ++kk) fma2(a2p[kk], wb, sr[kk]);
            }
        }
        __syncthreads();
        {
            float bi = __ldg(b_out1 + c0h);
            float* op = o1buf + c0h * O1S + jh;
            #pragma unroll
            for (int kk = 0; kk < 13; ++kk) {
                float2 v = up2(a2p[kk]);
                float v0 = v.x + bi; v0 = v0 > 0.0f ? v0 : 0.0f;
                float v1 = v.y + bi; v1 = v1 > 0.0f ? v1 : 0.0f;
                *reinterpret_cast<u64*>(op + 2 * kk) = pk2(v0, v1);
            }
        }
        __syncthreads();
        // ---- out2 ----
        u64 a3p[13];
        #pragma unroll
        for (int kk = 0; kk < 13; ++kk) a3p[kk] = 0ULL;
        for (int kch = 0; kch < 16; ++kch) {
            const int kb = kch * 16;
            __syncthreads();
            for (int idx = tid; idx < 4096; idx += NT) {
                int k = idx & 15; int c = idx >> 4;
                wst[k * 260 + c] = w_out2[c * CS_ + kb + k];
            }
            __syncthreads();
            #pragma unroll
            for (int k = 0; k < 16; ++k) {
                u64 wb = bc2(wst[k * 260 + c0h]);
                const u64* orr = reinterpret_cast<const u64*>(o1buf + (kb + k) * O1S + jh);
                #pragma unroll
                for (int kk = 0; kk < 13; ++kk) fma2(a3p[kk], wb, orr[kk]);
            }
        }
        // write to gmem
        {
            float bo = __ldg(b_out2 + c0h);
            float* orow = out + ((size_t)bb * V_ + c0h) * T_;
            #pragma unroll
            for (int kk = 0; kk < 13; ++kk) {
                int t = t0 + jbase + jh + 2 * kk;
                float2 v = up2(a3p[kk]);
                v.x += bo; v.y += bo;
                if (t + 1 < T_) {
                    *reinterpret_cast<float2*>(orow + t) = v;
                } else if (t < T_) {
                    orow[t] = v.x;
                }
            }
        }
        __syncthreads();
    }
}

extern "C" void kernel_launch(void* const* d_in, const int* in_sizes, int n_in,
                              void* d_out, int out_size) {
    const int*   tokens = (const int*)  d_in[0];
    const float* emb    = (const float*)d_in[1];
    const float* w_init = (const float*)d_in[2];
    const float* b_init = (const float*)d_in[3];
    const float* w_dil  = (const float*)d_in[4];
    const float* b_dil  = (const float*)d_in[5];
    const float* w_res  = (const float*)d_in[6];
    const float* b_res  = (const float*)d_in[7];
    const float* w_skip = (const float*)d_in[8];
    const float* b_skip = (const float*)d_in[9];
    const float* w_out1 = (const float*)d_in[10];
    const float* b_out1 = (const float*)d_in[11];
    const float* w_out2 = (const float*)d_in[12];
    const float* b_out2 = (const float*)d_in[13];
    float* out = (float*)d_out;

    cudaFuncSetAttribute(wavenet_fused, cudaFuncAttributeMaxDynamicSharedMemorySize, SMEM_BYTES);
    dim3 grid((T_ + TT - 1) / TT, B_);
    wavenet_fused<<<grid, NT, SMEM_BYTES>>>(
        tokens, emb, w_init, b_init, w_dil, b_dil, w_res, b_res,
        w_skip, b_skip, w_out1, b_out1, w_out2, b_out2, out);
}

// round 4
// speedup vs baseline: 1.2687x; 1.2412x over previous
#include <cuda_runtime.h>
#include <cuda_bf16.h>
#include <math.h>

// Problem constants
#define B_   16
#define T_   8192
#define V_   256
#define CE_  256
#define CR_  128
#define CS_  256
#define GC_  64
#define L_   12

// Tiling
#define TT   104
#define WP   128
#define XS   132
#define SKS  106
#define NT   512
#define O1S  56

// smem layout (floats)
#define OFF_BUFA 0
#define N_BUFA   (128*XS)
#define OFF_GBUF (OFF_BUFA + N_BUFA)
#define N_GBUF   (64*XS)              // 8448 (also dilated-conv weight staging: 32*260=8320)
#define OFF_SKIP (OFF_GBUF + N_GBUF)
#define N_SKIP   (CS_*SKS)
#define OFF_WST  (OFF_SKIP + N_SKIP)
#define N_WST    4160
#define OFF_TOK  (OFF_WST + N_WST)
#define SMEM_BYTES ((OFF_TOK)*4 + 132*4)

typedef unsigned long long u64;

__device__ __forceinline__ u64 pk2(float lo, float hi) {
    u64 r; asm("mov.b64 %0, {%1,%2};" : "=l"(r) : "f"(lo), "f"(hi)); return r;
}
__device__ __forceinline__ u64 bc2(float x) { return pk2(x, x); }
__device__ __forceinline__ void fma2(u64& d, u64 a, u64 b) {
    asm("fma.rn.f32x2 %0, %1, %2, %0;" : "+l"(d) : "l"(a), "l"(b));
}
__device__ __forceinline__ u64 add2(u64 a, u64 b) {
    u64 r; asm("add.rn.f32x2 %0, %1, %2;" : "=l"(r) : "l"(a), "l"(b)); return r;
}
__device__ __forceinline__ float2 up2(u64 a) {
    float2 f; asm("mov.b64 {%0,%1}, %2;" : "=f"(f.x), "=f"(f.y) : "l"(a)); return f;
}
__device__ __forceinline__ float sigmoidf_(float x) {
    return __fdividef(1.0f, 1.0f + __expf(-x));
}

__global__ void __launch_bounds__(NT, 1) wavenet_fused(
    const int*   __restrict__ tokens,
    const float* __restrict__ emb,
    const float* __restrict__ w_init, const float* __restrict__ b_init,
    const float* __restrict__ w_dil,  const float* __restrict__ b_dil,
    const float* __restrict__ w_res,  const float* __restrict__ b_res,
    const float* __restrict__ w_skip, const float* __restrict__ b_skip,
    const float* __restrict__ w_out1, const float* __restrict__ b_out1,
    const float* __restrict__ w_out2, const float* __restrict__ b_out2,
    float* __restrict__ out)
{
    extern __shared__ float sm[];
    float* bufA  = sm + OFF_BUFA;   // x activations [128][XS]
    float* gbuf  = sm + OFF_GBUF;   // gate output [64][XS]; also conv-weight staging
    float* skipS = sm + OFF_SKIP;   // skip accum [256][SKS]
    float* wst   = sm + OFF_WST;    // small weight staging
    int*   tokb  = (int*)(sm + OFF_TOK);

    const int tid  = threadIdx.x;
    const int tile = blockIdx.x;
    const int bb   = blockIdx.y;
    const int t0   = tile * TT;
    const int pzero = (tile == 0) ? 24 : 0;

    for (int q = tid; q < WP + 1; q += NT) {
        int t = t0 - 25 + q;
        tokb[q] = (t >= 0 && t < T_) ? tokens[bb * T_ + t] : -1;
    }
    for (int i = tid; i < N_SKIP; i += NT) skipS[i] = 0.0f;

    // conv thread mapping: cg(0..31) channel group, pg(0..15) position group.
    // thread owns channels {c0,c0+1,c0+64,c0+65} and position PAIRS q0+32k, k=0..3
    const int cg = tid >> 4;
    const int pg = tid & 15;
    const int c0 = 2 * cg;
    const int q0 = 2 * pg;

    // ======================= init conv (emb -> x0) =======================
    {
        u64 acc[4][4];
        #pragma unroll
        for (int ic = 0; ic < 4; ++ic)
            #pragma unroll
            for (int k = 0; k < 4; ++k) acc[ic][k] = 0ULL;

        __syncthreads();
        for (int ch = 0; ch < 16; ++ch) {       // ce chunks of 16
            const int ceb = ch * 16;
            for (int idx = tid; idx < (WP + 1) * 4; idx += NT) {
                int q = idx >> 2; int ce4 = (idx & 3) << 2;
                int tok = tokb[q];
                float4 v = make_float4(0.f, 0.f, 0.f, 0.f);
                if (tok >= 0) v = *reinterpret_cast<const float4*>(emb + tok * CE_ + ceb + ce4);
                gbuf[(ce4 + 0) * XS + q] = v.x;
                gbuf[(ce4 + 1) * XS + q] = v.y;
                gbuf[(ce4 + 2) * XS + q] = v.z;
                gbuf[(ce4 + 3) * XS + q] = v.w;
            }
            // tap-split staging: wst[ce*260 + tap*128 + co]
            for (int idx = tid; idx < 2048; idx += NT) {
                int ce = idx & 15; int co = idx >> 4;
                float2 w2 = *reinterpret_cast<const float2*>(w_init + ((co * CE_ + ceb + ce) << 1));
                wst[ce * 260 + co]       = w2.x;
                wst[ce * 260 + 128 + co] = w2.y;
            }
            __syncthreads();
            #pragma unroll
            for (int ce = 0; ce < 16; ++ce) {
                const float* hr = gbuf + ce * XS;
                const float* wr = wst + ce * 260;
                u64 w00 = bc2(wr[c0]),        w10 = bc2(wr[128 + c0]);
                u64 w01 = bc2(wr[c0 + 1]),    w11 = bc2(wr[128 + c0 + 1]);
                u64 w02 = bc2(wr[c0 + 64]),   w12 = bc2(wr[128 + c0 + 64]);
                u64 w03 = bc2(wr[c0 + 65]),   w13 = bc2(wr[128 + c0 + 65]);
                #pragma unroll
                for (int k = 0; k < 4; ++k) {
                    int q = q0 + 32 * k;
                    u64 A = *reinterpret_cast<const u64*>(hr + q);     // h[q], h[q+1]
                    float s = hr[q + 2];
                    float2 av = up2(A);
                    u64 T1 = pk2(av.y, s);                              // h[q+1], h[q+2]
                    fma2(acc[0][k], w00, A); fma2(acc[0][k], w10, T1);
                    fma2(acc[1][k], w01, A); fma2(acc[1][k], w11, T1);
                    fma2(acc[2][k], w02, A); fma2(acc[2][k], w12, T1);
                    fma2(acc[3][k], w03, A); fma2(acc[3][k], w13, T1);
                }
            }
            __syncthreads();
        }
        #pragma unroll
        for (int ic = 0; ic < 4; ++ic) {
            int co = (ic < 2) ? (c0 + ic) : (c0 + 62 + ic);
            u64 bp = bc2(__ldg(b_init + co));
            #pragma unroll
            for (int k = 0; k < 4; ++k) {
                int q = q0 + 32 * k;
                u64 v = (q < pzero) ? 0ULL : add2(acc[ic][k], bp);
                *reinterpret_cast<u64*>(bufA + co * XS + q) = v;
            }
        }
    }
    __syncthreads();

    // skip-GEMM thread mapping
    const int cs0 = 2 * (tid >> 2);
    const int j0  = 26 * (tid & 3);

    float* wstD = gbuf;   // dilated conv weight staging overlays gbuf (dead during conv)

    // ============================ layers ============================
    for (int l = 0; l < L_; ++l) {
        // ---- dilated conv (k=2, d=2) ----
        u64 acc2[4][4];
        #pragma unroll
        for (int ic = 0; ic < 4; ++ic)
            #pragma unroll
            for (int k = 0; k < 4; ++k) acc2[ic][k] = 0ULL;

        const float* wd = w_dil + (size_t)l * CR_ * CR_ * 2;
        for (int ch = 0; ch < 4; ++ch) {        // ci chunks of 32
            const int cib = ch * 32;
            __syncthreads();   // gbuf free (prev consumers done)
            for (int idx = tid; idx < 4096; idx += NT) {
                int ci = idx & 31; int co = idx >> 5;
                float2 w2 = *reinterpret_cast<const float2*>(wd + ((co * CR_ + cib + ci) << 1));
                *reinterpret_cast<u64*>(wstD + ci * 260 + 2 * co) = pk2(w2.x, w2.y);
            }
            __syncthreads();
            #pragma unroll
            for (int ci = 0; ci < 32; ++ci) {
                const float* xr = bufA + (cib + ci) * XS;
                u64 xm[4], xp[4];
                xm[0] = (q0 >= 2) ? *reinterpret_cast<const u64*>(xr + q0 - 2) : 0ULL;
                xp[0] = *reinterpret_cast<const u64*>(xr + q0);
                #pragma unroll
                for (int k = 1; k < 4; ++k) {
                    xm[k] = *reinterpret_cast<const u64*>(xr + q0 + 32 * k - 2);
                    xp[k] = *reinterpret_cast<const u64*>(xr + q0 + 32 * k);
                }
                const float* wr = wstD + ci * 260 + 2 * c0;
                float4 wlo = *reinterpret_cast<const float4*>(wr);
                float4 whi = *reinterpret_cast<const float4*>(wr + 128);
                u64 b0 = bc2(wlo.x), b1 = bc2(wlo.y), b2 = bc2(wlo.z), b3 = bc2(wlo.w);
                u64 b4 = bc2(whi.x), b5 = bc2(whi.y), b6 = bc2(whi.z), b7 = bc2(whi.w);
                #pragma unroll
                for (int k = 0; k < 4; ++k) {
                    fma2(acc2[0][k], b0, xm[k]); fma2(acc2[0][k], b1, xp[k]);
                    fma2(acc2[1][k], b2, xm[k]); fma2(acc2[1][k], b3, xp[k]);
                    fma2(acc2[2][k], b4, xm[k]); fma2(acc2[2][k], b5, xp[k]);
                    fma2(acc2[3][k], b6, xm[k]); fma2(acc2[3][k], b7, xp[k]);
                }
            }
        }
        __syncthreads();   // conv reads of wstD(gbuf) done before gate writes gbuf
        // ---- gate ----
        {
            const float* bd = b_dil + l * CR_;
            float gb0 = __ldg(bd + c0), gb1 = __ldg(bd + c0 + 1);
            float gb2 = __ldg(bd + c0 + 64), gb3 = __ldg(bd + c0 + 65);
            #pragma unroll
            for (int k = 0; k < 4; ++k) {
                int q = q0 + 32 * k;
                float2 a0 = up2(acc2[0][k]);
                float2 a1 = up2(acc2[1][k]);
                float2 a2v = up2(acc2[2][k]);
                float2 a3v = up2(acc2[3][k]);
                float g0a = tanhf(a0.x + gb0) * sigmoidf_(a2v.x + gb2);
                float g0b = tanhf(a0.y + gb0) * sigmoidf_(a2v.y + gb2);
                float g1a = tanhf(a1.x + gb1) * sigmoidf_(a3v.x + gb3);
                float g1b = tanhf(a1.y + gb1) * sigmoidf_(a3v.y + gb3);
                *reinterpret_cast<u64*>(gbuf + c0 * XS + q)       = pk2(g0a, g0b);
                *reinterpret_cast<u64*>(gbuf + (c0 + 1) * XS + q) = pk2(g1a, g1b);
            }
        }
        __syncthreads();

        // ---- skip accumulation ----
        {
            const float* wsk = w_skip + (size_t)l * CS_ * GC_;
            u64 sacc0[13], sacc1[13];
            #pragma unroll
            for (int kk = 0; kk < 13; ++kk) { sacc0[kk] = 0ULL; sacc1[kk] = 0ULL; }
            for (int gch = 0; gch < 4; ++gch) {
                const int gcb = gch * 16;
                for (int idx = tid; idx < 4096; idx += NT) {
                    int gc = idx & 15; int cs = idx >> 4;
                    wst[gc * 260 + cs] = wsk[cs * GC_ + gcb + gc];
                }
                __syncthreads();
                #pragma unroll
                for (int gc = 0; gc < 16; ++gc) {
                    const float* wrow = wst + gc * 260;
                    u64 wb0 = bc2(wrow[cs0]);
                    u64 wb1 = bc2(wrow[cs0 + 1]);
                    const u64* gr = reinterpret_cast<const u64*>(gbuf + (gcb + gc) * XS + 24 + j0);
                    #pragma unroll
                    for (int kk = 0; kk < 13; ++kk) {
                        u64 gv = gr[kk];
                        fma2(sacc0[kk], wb0, gv);
                        fma2(sacc1[kk], wb1, gv);
                    }
                }
                __syncthreads();
            }
            const float* bsk = b_skip + l * CS_;
            u64 bbp0 = bc2(__ldg(bsk + cs0));
            u64 bbp1 = bc2(__ldg(bsk + cs0 + 1));
            u64* sp0 = reinterpret_cast<u64*>(skipS + cs0 * SKS + j0);
            u64* sp1 = reinterpret_cast<u64*>(skipS + (cs0 + 1) * SKS + j0);
            #pragma unroll
            for (int kk = 0; kk < 13; ++kk) {
                sp0[kk] = add2(sp0[kk], add2(sacc0[kk], bbp0));
                sp1[kk] = add2(sp1[kk], add2(sacc1[kk], bbp1));
            }
        }

        // ---- residual: x = x + W_res g (+b) ----
        {
            const float* wrp = w_res + (size_t)l * CR_ * GC_;
            u64 racc[4][4];
            #pragma unroll
            for (int ic = 0; ic < 4; ++ic)
                #pragma unroll
                for (int k = 0; k < 4; ++k) racc[ic][k] = 0ULL;
            for (int gch = 0; gch < 2; ++gch) {
                const int gcb = gch * 32;
                __syncthreads();
                for (int idx = tid; idx < 4096; idx += NT) {
                    int gc = idx & 31; int co = idx >> 5;
                    wst[gc * 130 + co] = wrp[co * GC_ + gcb + gc];
                }
                __syncthreads();
                #pragma unroll
                for (int gc = 0; gc < 32; ++gc) {
                    const float* grow = gbuf + (gcb + gc) * XS;
                    u64 g0 = *reinterpret_cast<const u64*>(grow + q0);
                    u64 g1 = *reinterpret_cast<const u64*>(grow + q0 + 32);
                    u64 g2 = *reinterpret_cast<const u64*>(grow + q0 + 64);
                    u64 g3 = *reinterpret_cast<const u64*>(grow + q0 + 96);
                    const float* wrow = wst + gc * 130;
                    float2 wlo = *reinterpret_cast<const float2*>(wrow + c0);
                    float2 whi = *reinterpret_cast<const float2*>(wrow + c0 + 64);
                    u64 w0 = bc2(wlo.x), w1 = bc2(wlo.y), w2 = bc2(whi.x), w3 = bc2(whi.y);
                    fma2(racc[0][0], w0, g0); fma2(racc[0][1], w0, g1);
                    fma2(racc[0][2], w0, g2); fma2(racc[0][3], w0, g3);
                    fma2(racc[1][0], w1, g0); fma2(racc[1][1], w1, g1);
                    fma2(racc[1][2], w1, g2); fma2(racc[1][3], w1, g3);
                    fma2(racc[2][0], w2, g0); fma2(racc[2][1], w2, g1);
                    fma2(racc[2][2], w2, g2); fma2(racc[2][3], w2, g3);
                    fma2(racc[3][0], w3, g0); fma2(racc[3][1], w3, g1);
                    fma2(racc[3][2], w3, g2); fma2(racc[3][3], w3, g3);
                }
            }
            __syncthreads();
            const float* br = b_res + l * CR_;
            #pragma unroll
            for (int ic = 0; ic < 4; ++ic) {
                int co = (ic < 2) ? (c0 + ic) : (c0 + 62 + ic);
                u64 bp = bc2(__ldg(br + co));
                u64* xrow0 = reinterpret_cast<u64*>(bufA + co * XS);
                #pragma unroll
                for (int k = 0; k < 4; ++k) {
                    int q = q0 + 32 * k;
                    u64* xp_ = reinterpret_cast<u64*>(bufA + co * XS + q);
                    u64 v = add2(*xp_, add2(racc[ic][k], bp));
                    if (q < pzero) v = 0ULL;
                    *xp_ = v;
                }
                (void)xrow0;
            }
        }
        __syncthreads();
    }

    // ======================= output head =======================
    for (int i = tid; i < N_SKIP; i += NT) {
        float v = skipS[i] * (1.0f / 12.0f);
        skipS[i] = v > 0.0f ? v : 0.0f;
    }

    float* o1buf = bufA;
    const int c0h = tid >> 1;
    const int jh  = 26 * (tid & 1);

    for (int half = 0; half < 2; ++half) {
        const int jbase = half * 52;
        // ---- out1 ----
        u64 a2p[13];
        #pragma unroll
        for (int kk = 0; kk < 13; ++kk) a2p[kk] = 0ULL;
        for (int kch = 0; kch < 16; ++kch) {
            const int kb = kch * 16;
            __syncthreads();
            for (int idx = tid; idx < 4096; idx += NT) {
                int k = idx & 15; int c = idx >> 4;
                wst[k * 260 + c] = w_out1[c * CS_ + kb + k];
            }
            __syncthreads();
            #pragma unroll
            for (int k = 0; k < 16; ++k) {
                u64 wb = bc2(wst[k * 260 + c0h]);
                const u64* sr = reinterpret_cast<const u64*>(skipS + (kb + k) * SKS + jbase + jh);
                #pragma unroll
                for (int kk = 0; kk < 13; ++kk) fma2(a2p[kk], wb, sr[kk]);
            }
        }
        __syncthreads();
        {
            float bi = __ldg(b_out1 + c0h);
            float* op = o1buf + c0h * O1S + jh;
            #pragma unroll
            for (int kk = 0; kk < 13; ++kk) {
                float2 v = up2(a2p[kk]);
                float v0 = v.x + bi; v0 = v0 > 0.0f ? v0 : 0.0f;
                float v1 = v.y + bi; v1 = v1 > 0.0f ? v1 : 0.0f;
                *reinterpret_cast<u64*>(op + 2 * kk) = pk2(v0, v1);
            }
        }
        __syncthreads();
        // ---- out2 ----
        u64 a3p[13];
        #pragma unroll
        for (int kk = 0; kk < 13; ++kk) a3p[kk] = 0ULL;
        for (int kch = 0; kch < 16; ++kch) {
            const int kb = kch * 16;
            __syncthreads();
            for (int idx = tid; idx < 4096; idx += NT) {
                int k = idx & 15; int c = idx >> 4;
                wst[k * 260 + c] = w_out2[c * CS_ + kb + k];
            }
            __syncthreads();
            #pragma unroll
            for (int k = 0; k < 16; ++k) {
                u64 wb = bc2(wst[k * 260 + c0h]);
                const u64* orr = reinterpret_cast<const u64*>(o1buf + (kb + k) * O1S + jh);
                #pragma unroll
                for (int kk = 0; kk < 13; ++kk) fma2(a3p[kk], wb, orr[kk]);
            }
        }
        {
            float bo = __ldg(b_out2 + c0h);
            float* orow = out + ((size_t)bb * V_ + c0h) * T_;
            #pragma unroll
            for (int kk = 0; kk < 13; ++kk) {
                int t = t0 + jbase + jh + 2 * kk;
                float2 v = up2(a3p[kk]);
                v.x += bo; v.y += bo;
                if (t + 1 < T_) {
                    *reinterpret_cast<float2*>(orow + t) = v;
                } else if (t < T_) {
                    orow[t] = v.x;
                }
            }
        }
        __syncthreads();
    }
}

extern "C" void kernel_launch(void* const* d_in, const int* in_sizes, int n_in,
                              void* d_out, int out_size) {
    const int*   tokens = (const int*)  d_in[0];
    const float* emb    = (const float*)d_in[1];
    const float* w_init = (const float*)d_in[2];
    const float* b_init = (const float*)d_in[3];
    const float* w_dil  = (const float*)d_in[4];
    const float* b_dil  = (const float*)d_in[5];
    const float* w_res  = (const float*)d_in[6];
    const float* b_res  = (const float*)d_in[7];
    const float* w_skip = (const float*)d_in[8];
    const float* b_skip = (const float*)d_in[9];
    const float* w_out1 = (const float*)d_in[10];
    const float* b_out1 = (const float*)d_in[11];
    const float* w_out2 = (const float*)d_in[12];
    const float* b_out2 = (const float*)d_in[13];
    float* out = (float*)d_out;

    cudaFuncSetAttribute(wavenet_fused, cudaFuncAttributeMaxDynamicSharedMemorySize, SMEM_BYTES);
    dim3 grid((T_ + TT - 1) / TT, B_);
    wavenet_fused<<<grid, NT, SMEM_BYTES>>>(
        tokens, emb, w_init, b_init, w_dil, b_dil, w_res, b_res,
        w_skip, b_skip, w_out1, b_out1, w_out2, b_out2, out);
}